// round 15
// baseline (speedup 1.0000x reference)
#include <cuda_runtime.h>
#include <cuda_bf16.h>
#include <math.h>
#include <stdint.h>

#define NN 100000
#define EE 1250000
#define TT 8

// ---------------- device scratch (static, no allocation) ----------------
__device__ __align__(128) int   g_deg[NN];
__device__ __align__(128) int   g_cnt[NN];
__device__ __align__(128) int   g_cursor[NN];
__device__ __align__(128) int   g_rowptr[NN + 1];
__device__ __align__(128) int   g_bsum[256];
__device__ __align__(128) int   g_boff[256];
__device__ __align__(128) float g_dinv[NN];
__device__ __align__(128) int2  g_cw[EE];
__device__ int g_is64;

// bf2 packed activations: u32 = ushort(bf16_hi) | ushort(bf16_lo)<<16
__device__ __align__(128) uint32_t g_mvxA[(size_t)TT * NN * 64];
__device__ __align__(128) uint32_t g_h2[(size_t)NN * 64];
__device__ __align__(128) uint32_t g_mvh2[(size_t)NN * 64];
__device__ __align__(128) uint32_t g_hr2[(size_t)NN * 64];
__device__ __align__(128) uint32_t g_mvhr2[(size_t)NN * 64];
__device__ __align__(128) float    g_h[(size_t)NN * 64];
__device__ __align__(128) float    g_z[(size_t)NN * 64];

// packed bf16 weights, linear layout: [chunk(4)][hi/lo(2)][k(64)][n(BN)]
__device__ __align__(128) __nv_bfloat16 g_Bzr[4 * 2 * 64 * 128];
__device__ __align__(128) __nv_bfloat16 g_Bh[4 * 2 * 64 * 64];

__device__ __align__(128) float g_bz[64];
__device__ __align__(128) float g_br[64];
__device__ __align__(128) float g_bh[64];

// ---------------- helpers ----------------
__device__ __forceinline__ uint32_t smem_u32(const void* p) {
    uint32_t a;
    asm("{ .reg .u64 t; cvta.to.shared.u64 t, %1; cvt.u32.u64 %0, t; }" : "=r"(a) : "l"(p));
    return a;
}
__device__ __forceinline__ void ldm_x4(uint32_t* r, uint32_t a) {
    asm volatile("ldmatrix.sync.aligned.m8n8.x4.shared.b16 {%0,%1,%2,%3}, [%4];"
        : "=r"(r[0]), "=r"(r[1]), "=r"(r[2]), "=r"(r[3]) : "r"(a));
}
__device__ __forceinline__ void ldm_x4t(uint32_t* r, uint32_t a) {
    asm volatile("ldmatrix.sync.aligned.m8n8.x4.trans.shared.b16 {%0,%1,%2,%3}, [%4];"
        : "=r"(r[0]), "=r"(r[1]), "=r"(r[2]), "=r"(r[3]) : "r"(a));
}
__device__ __forceinline__ void mma16816(float* c, const uint32_t* a, uint32_t b0, uint32_t b1) {
    asm volatile("mma.sync.aligned.m16n8k16.row.col.f32.bf16.bf16.f32 "
        "{%0,%1,%2,%3}, {%4,%5,%6,%7}, {%8,%9}, {%0,%1,%2,%3};"
        : "+f"(c[0]), "+f"(c[1]), "+f"(c[2]), "+f"(c[3])
        : "r"(a[0]), "r"(a[1]), "r"(a[2]), "r"(a[3]), "r"(b0), "r"(b1));
}
__device__ __forceinline__ uint32_t pack_bf2(float v) {
    __nv_bfloat16 hb = __float2bfloat16(v);
    __nv_bfloat16 lb = __float2bfloat16(v - __bfloat162float(hb));
    return (uint32_t)__bfloat16_as_ushort(hb) | ((uint32_t)__bfloat16_as_ushort(lb) << 16);
}
__device__ __forceinline__ float unpack_bf2(uint32_t u) {
    return __uint_as_float(u << 16) + __uint_as_float(u & 0xFFFF0000u);
}
__device__ __forceinline__ uint32_t hi_pair(float a, float b) {
    return (uint32_t)__bfloat16_as_ushort(__float2bfloat16(a))
         | ((uint32_t)__bfloat16_as_ushort(__float2bfloat16(b)) << 16);
}
__device__ __forceinline__ uint32_t lo_pair(float a, float b) {
    float ha = __bfloat162float(__float2bfloat16(a));
    float hb = __bfloat162float(__float2bfloat16(b));
    return (uint32_t)__bfloat16_as_ushort(__float2bfloat16(a - ha))
         | ((uint32_t)__bfloat16_as_ushort(__float2bfloat16(b - hb)) << 16);
}
__device__ __forceinline__ int load_idx(const void* ei, size_t i) {
    if (g_is64) return (int)((const long long*)ei)[i];
    return ((const int*)ei)[i];
}

// ---------------- mega setup kernel (launch 0) ----------------
__global__ void k_init(const int* __restrict__ ei,
                       const float* __restrict__ Wxz, const float* __restrict__ Whz,
                       const float* __restrict__ Wxr, const float* __restrict__ Whr,
                       const float* __restrict__ Wxh, const float* __restrict__ Whh,
                       const float* __restrict__ bxz, const float* __restrict__ bhz,
                       const float* __restrict__ bxr, const float* __restrict__ bhr,
                       const float* __restrict__ bxh, const float* __restrict__ bhh) {
    const size_t gid = (size_t)blockIdx.x * blockDim.x + threadIdx.x;
    const size_t stride = (size_t)gridDim.x * blockDim.x;

    if (gid == 0) {
        int is64 = 1;
        for (int i = 0; i < 512; i++)
            if (ei[2 * i + 1] != 0) { is64 = 0; break; }
        g_is64 = is64;
    }
    for (size_t i = gid; i < NN; i += stride) {
        g_deg[i] = 0; g_cnt[i] = 0; g_cursor[i] = 0;
    }
    for (size_t i = gid; i < (size_t)NN * 64; i += stride) {
        g_h[i] = 0.0f; g_h2[i] = 0u;
    }
    for (size_t i = gid; i < 256 * 128; i += stride) {
        int k = (int)(i >> 7), nout = (int)(i & 127);
        int kb = k >> 6, kr = k & 63;
        const float* W; int cc;
        if (nout < 64) { W = (kb < 2) ? Wxz : Whz; cc = nout; }
        else           { W = (kb < 2) ? Wxr : Whr; cc = nout - 64; }
        float v = W[(kb & 1) * 4096 + kr * 64 + cc];
        __nv_bfloat16 hb = __float2bfloat16(v);
        __nv_bfloat16 lb = __float2bfloat16(v - __bfloat162float(hb));
        int base = kb * 16384 + kr * 128 + nout;
        g_Bzr[base]        = hb;
        g_Bzr[base + 8192] = lb;
    }
    for (size_t i = gid; i < 256 * 64; i += stride) {
        int k = (int)(i >> 6), nout = (int)(i & 63);
        int kb = k >> 6, kr = k & 63;
        const float* W = (kb < 2) ? Wxh : Whh;
        float v = W[(kb & 1) * 4096 + kr * 64 + nout];
        __nv_bfloat16 hb = __float2bfloat16(v);
        __nv_bfloat16 lb = __float2bfloat16(v - __bfloat162float(hb));
        int base = kb * 8192 + kr * 64 + nout;
        g_Bh[base]        = hb;
        g_Bh[base + 4096] = lb;
    }
    for (size_t i = gid; i < 64; i += stride) {
        g_bz[i] = bxz[i] + bhz[i];
        g_br[i] = bxr[i] + bhr[i];
        g_bh[i] = bxh[i] + bhh[i];
    }
}

// ---------------- setup kernels ----------------
__global__ void k_hist(const void* __restrict__ ei, int E) {
    int e = blockIdx.x * blockDim.x + threadIdx.x;
    if (e < E) {
        int s = load_idx(ei, e);
        int d = load_idx(ei, (size_t)E + e);
        if (s >= 0 && s < NN) atomicAdd(&g_deg[s], 1);
        if (d >= 0 && d < NN) atomicAdd(&g_cnt[d], 1);
    }
}
__global__ void k_dinv(int n) {
    int i = blockIdx.x * blockDim.x + threadIdx.x;
    if (i < n) {
        int d = g_deg[i];
        g_dinv[i] = (d > 0) ? rsqrtf((float)d) : 0.0f;
    }
}
__global__ void k_scan1(int n) {
    __shared__ int s[1024];
    int tid = threadIdx.x;
    int gid = blockIdx.x * 1024 + tid;
    int v = (gid < n) ? g_cnt[gid] : 0;
    s[tid] = v;
    __syncthreads();
    #pragma unroll
    for (int off = 1; off < 1024; off <<= 1) {
        int t = (tid >= off) ? s[tid - off] : 0;
        __syncthreads();
        s[tid] += t;
        __syncthreads();
    }
    if (gid < n) g_rowptr[gid] = s[tid] - v;
    if (tid == 1023) g_bsum[blockIdx.x] = s[1023];
}
__global__ void k_scan2(int nb) {
    if (threadIdx.x == 0) {
        int acc = 0;
        for (int i = 0; i < nb; i++) { int t = g_bsum[i]; g_boff[i] = acc; acc += t; }
    }
}
__global__ void k_scan3(int n, int E) {
    int gid = blockIdx.x * blockDim.x + threadIdx.x;
    if (gid < n) g_rowptr[gid] += g_boff[gid >> 10];
    if (gid == 0) g_rowptr[n] = E;
}
__global__ void k_fill(const void* __restrict__ ei, int E) {
    int e = blockIdx.x * blockDim.x + threadIdx.x;
    if (e >= E) return;
    int s = load_idx(ei, e);
    int d = load_idx(ei, (size_t)E + e);
    if (s < 0 || s >= NN || d < 0 || d >= NN) return;
    int pos = g_rowptr[d] + atomicAdd(&g_cursor[d], 1);
    float w = -g_dinv[s] * g_dinv[d];
    g_cw[pos] = make_int2(s, __float_as_int(w));
}

// ---------------- spmv: warp per row, 4-edge unroll ----------------
// bf2-input variant (recurrent h / hr gathers)
__global__ void k_spmv2(const uint32_t* __restrict__ x, uint32_t* __restrict__ y, int n) {
    int row = blockIdx.x * 8 + (threadIdx.x >> 5);
    if (row >= n) return;
    int lane = threadIdx.x & 31;
    const uint2* x2 = reinterpret_cast<const uint2*>(x);
    int s = g_rowptr[row], e = g_rowptr[row + 1];
    float a0 = 0.0f, a1 = 0.0f;
    int p = s;
    for (; p + 4 <= e; p += 4) {
        int2 c0 = g_cw[p], c1 = g_cw[p + 1], c2 = g_cw[p + 2], c3 = g_cw[p + 3];
        uint2 v0 = __ldg(&x2[(size_t)c0.x * 32 + lane]);
        uint2 v1 = __ldg(&x2[(size_t)c1.x * 32 + lane]);
        uint2 v2 = __ldg(&x2[(size_t)c2.x * 32 + lane]);
        uint2 v3 = __ldg(&x2[(size_t)c3.x * 32 + lane]);
        float w0 = __int_as_float(c0.y), w1 = __int_as_float(c1.y);
        float w2 = __int_as_float(c2.y), w3 = __int_as_float(c3.y);
        a0 = fmaf(w0, unpack_bf2(v0.x), a0); a1 = fmaf(w0, unpack_bf2(v0.y), a1);
        a0 = fmaf(w1, unpack_bf2(v1.x), a0); a1 = fmaf(w1, unpack_bf2(v1.y), a1);
        a0 = fmaf(w2, unpack_bf2(v2.x), a0); a1 = fmaf(w2, unpack_bf2(v2.y), a1);
        a0 = fmaf(w3, unpack_bf2(v3.x), a0); a1 = fmaf(w3, unpack_bf2(v3.y), a1);
    }
    for (; p < e; p++) {
        int2 c = g_cw[p];
        uint2 v = __ldg(&x2[(size_t)c.x * 32 + lane]);
        float w = __int_as_float(c.y);
        a0 = fmaf(w, unpack_bf2(v.x), a0);
        a1 = fmaf(w, unpack_bf2(v.y), a1);
    }
    uint2 o = make_uint2(pack_bf2(a0), pack_bf2(a1));
    reinterpret_cast<uint2*>(y)[(size_t)row * 32 + lane] = o;
}

// fp32-input variant: x-side spmv for all timesteps, reads X directly
__global__ void k_spmv2_all(const float* __restrict__ X, int n) {
    int row = blockIdx.x * 8 + (threadIdx.x >> 5);
    if (row >= n) return;
    int t = blockIdx.y;
    int lane = threadIdx.x & 31;
    const float2* x2 = reinterpret_cast<const float2*>(X + (size_t)t * n * 64);
    int s = g_rowptr[row], e = g_rowptr[row + 1];
    float a0 = 0.0f, a1 = 0.0f;
    int p = s;
    for (; p + 4 <= e; p += 4) {
        int2 c0 = g_cw[p], c1 = g_cw[p + 1], c2 = g_cw[p + 2], c3 = g_cw[p + 3];
        float2 v0 = __ldg(&x2[(size_t)c0.x * 32 + lane]);
        float2 v1 = __ldg(&x2[(size_t)c1.x * 32 + lane]);
        float2 v2 = __ldg(&x2[(size_t)c2.x * 32 + lane]);
        float2 v3 = __ldg(&x2[(size_t)c3.x * 32 + lane]);
        float w0 = __int_as_float(c0.y), w1 = __int_as_float(c1.y);
        float w2 = __int_as_float(c2.y), w3 = __int_as_float(c3.y);
        a0 = fmaf(w0, v0.x, a0); a1 = fmaf(w0, v0.y, a1);
        a0 = fmaf(w1, v1.x, a0); a1 = fmaf(w1, v1.y, a1);
        a0 = fmaf(w2, v2.x, a0); a1 = fmaf(w2, v2.y, a1);
        a0 = fmaf(w3, v3.x, a0); a1 = fmaf(w3, v3.y, a1);
    }
    for (; p < e; p++) {
        int2 c = g_cw[p];
        float2 v = __ldg(&x2[(size_t)c.x * 32 + lane]);
        float w = __int_as_float(c.y);
        a0 = fmaf(w, v.x, a0);
        a1 = fmaf(w, v.y, a1);
    }
    uint2 o = make_uint2(pack_bf2(a0), pack_bf2(a1));
    reinterpret_cast<uint2*>(g_mvxA + (size_t)t * n * 64)[(size_t)row * 32 + lane] = o;
}

// ---------------- mma.sync GEMM core, BM=64, smem W ----------------
// C(64 x BN) = [X(fp32)|A1|A2|A3](64 x 256) @ W(256 x BN), bf16 3-split.
// Chunk 0 reads fp32 X and converts inline; chunks 1-3 read bf2 (prmt).
template <int BN, int THREADS>
__device__ __forceinline__ void mma_core(
    const float* __restrict__ A0f, const uint32_t* __restrict__ A1,
    const uint32_t* __restrict__ A2, const uint32_t* __restrict__ A3,
    const __nv_bfloat16* __restrict__ Bpk, int n,
    int warpRow, int warpCol, float (&acc)[8][4], char* sm)
{
    constexpr int BM = 64;
    constexpr int ASTR = 72;
    constexpr int A_BYTES = BM * ASTR * 2;     // 9216
    constexpr int WSTR = BN + 8;
    constexpr int W_BYTES = 64 * WSTR * 2;
    constexpr int W_OFF = 2 * A_BYTES;

    const int tid = threadIdx.x;
    const int lane = tid & 31;
    uint32_t s_a = smem_u32(sm);
    uint32_t s_w = s_a + W_OFF;

    const uint32_t* srcs[4] = {nullptr, A1, A2, A3};

    #pragma unroll 1
    for (int c = 0; c < 4; c++) {
        if (c) __syncthreads();

        // ---- A chunk: 64 x 64 -> hi/lo bf16 tiles ----
        constexpr int GROUPS = BM * 64 / (THREADS * 8);
        #pragma unroll
        for (int g = 0; g < GROUPS; g++) {
            int gi = g * THREADS + tid;
            int r  = gi >> 3;
            int kc = (gi & 7) * 8;
            int gr = blockIdx.x * BM + r;
            uint4 hv, lv;
            if (c == 0) {
                // fp32 source, convert+split inline
                float4 f0 = make_float4(0.f, 0.f, 0.f, 0.f);
                float4 f1 = make_float4(0.f, 0.f, 0.f, 0.f);
                if (gr < n) {
                    f0 = *reinterpret_cast<const float4*>(A0f + (size_t)gr * 64 + kc);
                    f1 = *reinterpret_cast<const float4*>(A0f + (size_t)gr * 64 + kc + 4);
                }
                hv.x = hi_pair(f0.x, f0.y); lv.x = lo_pair(f0.x, f0.y);
                hv.y = hi_pair(f0.z, f0.w); lv.y = lo_pair(f0.z, f0.w);
                hv.z = hi_pair(f1.x, f1.y); lv.z = lo_pair(f1.x, f1.y);
                hv.w = hi_pair(f1.z, f1.w); lv.w = lo_pair(f1.z, f1.w);
            } else {
                const uint32_t* src = srcs[c];
                uint4 p0 = make_uint4(0, 0, 0, 0), p1 = make_uint4(0, 0, 0, 0);
                if (gr < n) {
                    p0 = *reinterpret_cast<const uint4*>(src + (size_t)gr * 64 + kc);
                    p1 = *reinterpret_cast<const uint4*>(src + (size_t)gr * 64 + kc + 4);
                }
                hv.x = __byte_perm(p0.x, p0.y, 0x5410);
                hv.y = __byte_perm(p0.z, p0.w, 0x5410);
                hv.z = __byte_perm(p1.x, p1.y, 0x5410);
                hv.w = __byte_perm(p1.z, p1.w, 0x5410);
                lv.x = __byte_perm(p0.x, p0.y, 0x7632);
                lv.y = __byte_perm(p0.z, p0.w, 0x7632);
                lv.z = __byte_perm(p1.x, p1.y, 0x7632);
                lv.w = __byte_perm(p1.z, p1.w, 0x7632);
            }
            uint32_t off = (uint32_t)(r * ASTR + kc) * 2;
            *reinterpret_cast<uint4*>(sm + off)           = hv;
            *reinterpret_cast<uint4*>(sm + A_BYTES + off) = lv;
        }

        // ---- W chunk: linear global -> padded smem ----
        {
            const uint4* bs = reinterpret_cast<const uint4*>(Bpk + (size_t)c * 2 * 64 * BN);
            constexpr int ROWU4 = BN / 8;
            constexpr int TOT = 64 * ROWU4;
            #pragma unroll
            for (int sel = 0; sel < 2; sel++) {
                char* wd = sm + W_OFF + sel * W_BYTES;
                #pragma unroll
                for (int it = 0; it < TOT / THREADS; it++) {
                    int u = tid + it * THREADS;
                    int k = u / ROWU4, q = u % ROWU4;
                    *reinterpret_cast<uint4*>(wd + k * WSTR * 2 + q * 16) = bs[sel * TOT + u];
                }
            }
        }
        __syncthreads();

        // ---- compute: 4 ksteps of 16 ----
        #pragma unroll
        for (int ks = 0; ks < 4; ks++) {
            const int k0 = ks * 16;
            uint32_t ah[4], al[4];
            {
                int rowoff = warpRow + ((lane >> 3) & 1) * 8 + (lane & 7);
                int coloff = k0 + (lane >> 4) * 8;
                uint32_t ad = s_a + (uint32_t)(rowoff * ASTR + coloff) * 2;
                ldm_x4(ah, ad);
                ldm_x4(al, ad + A_BYTES);
            }
            #pragma unroll
            for (int nb2 = 0; nb2 < 4; nb2++) {
                int n0 = warpCol + nb2 * 16;
                uint32_t bd = s_w + (uint32_t)((k0 + (lane & 15)) * WSTR + n0 + (lane >> 4) * 8) * 2;
                uint32_t bh[4], bl[4];
                ldm_x4t(bh, bd);
                ldm_x4t(bl, bd + W_BYTES);
                mma16816(acc[2 * nb2 + 0], ah, bh[0], bh[1]);
                mma16816(acc[2 * nb2 + 0], al, bh[0], bh[1]);
                mma16816(acc[2 * nb2 + 0], ah, bl[0], bl[1]);
                mma16816(acc[2 * nb2 + 1], ah, bh[2], bh[3]);
                mma16816(acc[2 * nb2 + 1], al, bh[2], bh[3]);
                mma16816(acc[2 * nb2 + 1], ah, bl[2], bl[3]);
            }
        }
    }
}

__device__ __forceinline__ float sigmoidf_(float x) { return 1.0f / (1.0f + expf(-x)); }

// z/r GEMM: A = [x_t(fp32) | mvx | h | mvh], W = g_Bzr; BM=64, 8 warps.
__global__ __launch_bounds__(256)
void k_gemm_zr_mma(const float* __restrict__ xt, const uint32_t* __restrict__ mvx, int n) {
    extern __shared__ char sm[];
    const int w = threadIdx.x >> 5, lane = threadIdx.x & 31;
    const int warpRow = (w & 3) * 16;
    const int warpCol = (w >> 2) * 64;
    float acc[8][4] = {};
    mma_core<128, 256>(xt, mvx, g_h2, g_mvh2, g_Bzr, n, warpRow, warpCol, acc, sm);

    const bool isZ = (warpCol == 0);
    const int rbase = blockIdx.x * 64 + warpRow;
    #pragma unroll
    for (int h2 = 0; h2 < 2; h2++) {
        int row = rbase + (lane >> 2) + h2 * 8;
        if (row >= n) continue;
        #pragma unroll
        for (int nb = 0; nb < 8; nb++) {
            int cc = nb * 8 + (lane & 3) * 2;
            float v0 = acc[nb][h2 * 2 + 0];
            float v1 = acc[nb][h2 * 2 + 1];
            if (isZ) {
                float2 o;
                o.x = sigmoidf_(v0 + g_bz[cc]);
                o.y = sigmoidf_(v1 + g_bz[cc + 1]);
                *reinterpret_cast<float2*>(&g_z[(size_t)row * 64 + cc]) = o;
            } else {
                float2 hv = *reinterpret_cast<const float2*>(&g_h[(size_t)row * 64 + cc]);
                float r0 = sigmoidf_(v0 + g_br[cc])     * hv.x;
                float r1 = sigmoidf_(v1 + g_br[cc + 1]) * hv.y;
                uint2 o = make_uint2(pack_bf2(r0), pack_bf2(r1));
                *reinterpret_cast<uint2*>(&g_hr2[(size_t)row * 64 + cc]) = o;
            }
        }
    }
}

// h GEMM: A = [x_t(fp32) | mvx | hr | mvhr], W = g_Bh; BM=64, 4 warps.
__global__ __launch_bounds__(128)
void k_gemm_h_mma(const float* __restrict__ xt, const uint32_t* __restrict__ mvx, int n) {
    extern __shared__ char sm[];
    const int w = threadIdx.x >> 5, lane = threadIdx.x & 31;
    float acc[8][4] = {};
    mma_core<64, 128>(xt, mvx, g_hr2, g_mvhr2, g_Bh, n, w * 16, 0, acc, sm);

    const int rbase = blockIdx.x * 64 + w * 16;
    #pragma unroll
    for (int h2 = 0; h2 < 2; h2++) {
        int row = rbase + (lane >> 2) + h2 * 8;
        if (row >= n) continue;
        #pragma unroll
        for (int nb = 0; nb < 8; nb++) {
            int cc = nb * 8 + (lane & 3) * 2;
            float t0 = tanhf(acc[nb][h2 * 2 + 0] + g_bh[cc]);
            float t1 = tanhf(acc[nb][h2 * 2 + 1] + g_bh[cc + 1]);
            float2 zv = *reinterpret_cast<const float2*>(&g_z[(size_t)row * 64 + cc]);
            float2 hv = *reinterpret_cast<const float2*>(&g_h[(size_t)row * 64 + cc]);
            float2 o;
            o.x = zv.x * hv.x + (1.0f - zv.x) * t0;
            o.y = zv.y * hv.y + (1.0f - zv.y) * t1;
            *reinterpret_cast<float2*>(&g_h[(size_t)row * 64 + cc]) = o;
            uint2 o2 = make_uint2(pack_bf2(o.x), pack_bf2(o.y));
            *reinterpret_cast<uint2*>(&g_h2[(size_t)row * 64 + cc]) = o2;
        }
    }
}

// ---------------- final linear: out = h @ Wlin + blin (Nx64 @ 64x16) --------
__global__ __launch_bounds__(256)
void k_out(const float* __restrict__ Wlin, const float* __restrict__ blin,
           float* __restrict__ out, int n) {
    __shared__ float Ws[64][16];
    __shared__ float Hs[16][64];
    int tid = threadIdx.x;
    int rowBase = blockIdx.x * 16;
    #pragma unroll
    for (int i = 0; i < 4; i++) {
        int idx = tid + i * 256;
        reinterpret_cast<float*>(Ws)[idx] = Wlin[idx];
    }
    {
        int r = tid >> 4, c4 = tid & 15;
        int gr = rowBase + r;
        float4 v = make_float4(0.f, 0.f, 0.f, 0.f);
        if (gr < n) v = *reinterpret_cast<const float4*>(g_h + (size_t)gr * 64 + c4 * 4);
        *reinterpret_cast<float4*>(&Hs[r][c4 * 4]) = v;
    }
    __syncthreads();
    int r = tid >> 4, c = tid & 15;
    float s = blin[c];
    #pragma unroll
    for (int k = 0; k < 64; k++) s += Hs[r][k] * Ws[k][c];
    int gr = rowBase + r;
    if (gr < n) out[(size_t)gr * 16 + c] = s;
}

// ---------------- host orchestration (graph-capturable) ----------------
extern "C" void kernel_launch(void* const* d_in, const int* in_sizes, int n_in,
                              void* d_out, int out_size) {
    const float* X  = (const float*)d_in[0];
    const void*  EI = d_in[1];
    const float* Wxz = (const float*)d_in[2];
    const float* bxz = (const float*)d_in[3];
    const float* Whz = (const float*)d_in[4];
    const float* bhz = (const float*)d_in[5];
    const float* Wxr = (const float*)d_in[6];
    const float* bxr = (const float*)d_in[7];
    const float* Whr = (const float*)d_in[8];
    const float* bhr = (const float*)d_in[9];
    const float* Wxh = (const float*)d_in[10];
    const float* bxh = (const float*)d_in[11];
    const float* Whh = (const float*)d_in[12];
    const float* bhh = (const float*)d_in[13];
    const float* Wlin = (const float*)d_in[14];
    const float* blin = (const float*)d_in[15];
    float* out = (float*)d_out;

    const int n = NN;
    const int E = in_sizes[1] / 2;

    uint32_t *p_mvxA, *p_h2, *p_mvh2, *p_hr2, *p_mvhr2;
    cudaGetSymbolAddress((void**)&p_mvxA,  g_mvxA);
    cudaGetSymbolAddress((void**)&p_h2,    g_h2);
    cudaGetSymbolAddress((void**)&p_mvh2,  g_mvh2);
    cudaGetSymbolAddress((void**)&p_hr2,   g_hr2);
    cudaGetSymbolAddress((void**)&p_mvhr2, g_mvhr2);

    // BM=64 tiles: A 2*9216, W 2*64*(BN+8)*2
    const int SMEM_ZR = 2 * 9216 + 2 * 64 * (128 + 8) * 2;   // 53248
    const int SMEM_H  = 2 * 9216 + 2 * 64 * (64 + 8) * 2;    // 36864
    cudaFuncSetAttribute(k_gemm_zr_mma, cudaFuncAttributeMaxDynamicSharedMemorySize, SMEM_ZR);
    cudaFuncSetAttribute(k_gemm_h_mma,  cudaFuncAttributeMaxDynamicSharedMemorySize, SMEM_H);

    int ggrid = (n + 63) / 64;
    int nb = (n + 1023) / 1024;

    // setup (no X pre-split: GEMMs and spmv_all read fp32 X directly)
    k_init<<<1024, 256>>>((const int*)EI, Wxz, Whz, Wxr, Whr, Wxh, Whh,
                          bxz, bhz, bxr, bhr, bxh, bhh);
    k_hist<<<(E + 255) / 256, 256>>>(EI, E);
    k_dinv<<<(n + 255) / 256, 256>>>(n);
    k_scan1<<<nb, 1024>>>(n);
    k_scan2<<<1, 32>>>(nb);
    k_scan3<<<(n + 255) / 256, 256>>>(n, E);
    k_fill<<<(E + 255) / 256, 256>>>(EI, E);

    int sgrid = (n + 7) / 8;
    k_spmv2_all<<<dim3(sgrid, TT), 256>>>(X, n);

    for (int t = 0; t < TT; t++) {
        const float*    xt  = X      + (size_t)t * n * 64;
        const uint32_t* mvx = p_mvxA + (size_t)t * n * 64;
        k_spmv2<<<sgrid, 256>>>(p_h2, p_mvh2, n);
        k_gemm_zr_mma<<<ggrid, 256, SMEM_ZR>>>(xt, mvx, n);
        k_spmv2<<<sgrid, 256>>>(p_hr2, p_mvhr2, n);
        k_gemm_h_mma<<<ggrid, 128, SMEM_H>>>(xt, mvx, n);
    }

    k_out<<<(n + 15) / 16, 256>>>(Wlin, blin, out, n);
}

// round 16
// speedup vs baseline: 1.0728x; 1.0728x over previous
#include <cuda_runtime.h>
#include <cuda_bf16.h>
#include <math.h>
#include <stdint.h>

#define NN 100000
#define EE 1250000
#define TT 8

// ---------------- device scratch (static, no allocation) ----------------
__device__ __align__(128) int   g_deg[NN];
__device__ __align__(128) int   g_cnt[NN];
__device__ __align__(128) int   g_cursor[NN];
__device__ __align__(128) int   g_rowptr[NN + 1];
__device__ __align__(128) int   g_bsum[256];
__device__ __align__(128) int   g_boff[256];
__device__ __align__(128) float g_dinv[NN];
__device__ __align__(128) int2  g_cw[EE];
__device__ int g_is64;

// bf2 packed activations: u32 = ushort(bf16_hi) | ushort(bf16_lo)<<16
__device__ __align__(128) uint32_t g_X2[(size_t)TT * NN * 64];
__device__ __align__(128) uint32_t g_mvxA[(size_t)TT * NN * 64];
__device__ __align__(128) uint32_t g_h2[(size_t)NN * 64];
__device__ __align__(128) uint32_t g_mvh2[(size_t)NN * 64];
__device__ __align__(128) uint32_t g_hr2[(size_t)NN * 64];
__device__ __align__(128) uint32_t g_mvhr2[(size_t)NN * 64];
__device__ __align__(128) float    g_h[(size_t)NN * 64];
__device__ __align__(128) float    g_z[(size_t)NN * 64];

// packed bf16 weights, linear layout: [chunk(4)][hi/lo(2)][k(64)][n(BN)]
__device__ __align__(128) __nv_bfloat16 g_Bzr[4 * 2 * 64 * 128];
__device__ __align__(128) __nv_bfloat16 g_Bh[4 * 2 * 64 * 64];

__device__ __align__(128) float g_bz[64];
__device__ __align__(128) float g_br[64];
__device__ __align__(128) float g_bh[64];

// ---------------- helpers ----------------
__device__ __forceinline__ uint32_t smem_u32(const void* p) {
    uint32_t a;
    asm("{ .reg .u64 t; cvta.to.shared.u64 t, %1; cvt.u32.u64 %0, t; }" : "=r"(a) : "l"(p));
    return a;
}
__device__ __forceinline__ void ldm_x4(uint32_t* r, uint32_t a) {
    asm volatile("ldmatrix.sync.aligned.m8n8.x4.shared.b16 {%0,%1,%2,%3}, [%4];"
        : "=r"(r[0]), "=r"(r[1]), "=r"(r[2]), "=r"(r[3]) : "r"(a));
}
__device__ __forceinline__ void ldm_x4t(uint32_t* r, uint32_t a) {
    asm volatile("ldmatrix.sync.aligned.m8n8.x4.trans.shared.b16 {%0,%1,%2,%3}, [%4];"
        : "=r"(r[0]), "=r"(r[1]), "=r"(r[2]), "=r"(r[3]) : "r"(a));
}
__device__ __forceinline__ void mma16816(float* c, const uint32_t* a, uint32_t b0, uint32_t b1) {
    asm volatile("mma.sync.aligned.m16n8k16.row.col.f32.bf16.bf16.f32 "
        "{%0,%1,%2,%3}, {%4,%5,%6,%7}, {%8,%9}, {%0,%1,%2,%3};"
        : "+f"(c[0]), "+f"(c[1]), "+f"(c[2]), "+f"(c[3])
        : "r"(a[0]), "r"(a[1]), "r"(a[2]), "r"(a[3]), "r"(b0), "r"(b1));
}
__device__ __forceinline__ uint32_t pack_bf2(float v) {
    __nv_bfloat16 hb = __float2bfloat16(v);
    __nv_bfloat16 lb = __float2bfloat16(v - __bfloat162float(hb));
    return (uint32_t)__bfloat16_as_ushort(hb) | ((uint32_t)__bfloat16_as_ushort(lb) << 16);
}
__device__ __forceinline__ float unpack_bf2(uint32_t u) {
    return __uint_as_float(u << 16) + __uint_as_float(u & 0xFFFF0000u);
}
__device__ __forceinline__ int load_idx(const void* ei, size_t i) {
    if (g_is64) return (int)((const long long*)ei)[i];
    return ((const int*)ei)[i];
}

// ---------------- mega setup kernel (launch 0) ----------------
__global__ void k_init(const float* __restrict__ X, const int* __restrict__ ei,
                       const float* __restrict__ Wxz, const float* __restrict__ Whz,
                       const float* __restrict__ Wxr, const float* __restrict__ Whr,
                       const float* __restrict__ Wxh, const float* __restrict__ Whh,
                       const float* __restrict__ bxz, const float* __restrict__ bhz,
                       const float* __restrict__ bxr, const float* __restrict__ bhr,
                       const float* __restrict__ bxh, const float* __restrict__ bhh) {
    const size_t gid = (size_t)blockIdx.x * blockDim.x + threadIdx.x;
    const size_t stride = (size_t)gridDim.x * blockDim.x;

    if (gid == 0) {
        int is64 = 1;
        for (int i = 0; i < 512; i++)
            if (ei[2 * i + 1] != 0) { is64 = 0; break; }
        g_is64 = is64;
    }
    const size_t xtot4 = (size_t)TT * NN * 64 / 4;
    for (size_t i = gid; i < xtot4; i += stride) {
        float4 v = reinterpret_cast<const float4*>(X)[i];
        uint4 o;
        o.x = pack_bf2(v.x); o.y = pack_bf2(v.y);
        o.z = pack_bf2(v.z); o.w = pack_bf2(v.w);
        reinterpret_cast<uint4*>(g_X2)[i] = o;
    }
    for (size_t i = gid; i < NN; i += stride) {
        g_deg[i] = 0; g_cnt[i] = 0; g_cursor[i] = 0;
    }
    for (size_t i = gid; i < (size_t)NN * 64; i += stride) {
        g_h[i] = 0.0f; g_h2[i] = 0u;
    }
    for (size_t i = gid; i < 256 * 128; i += stride) {
        int k = (int)(i >> 7), nout = (int)(i & 127);
        int kb = k >> 6, kr = k & 63;
        const float* W; int cc;
        if (nout < 64) { W = (kb < 2) ? Wxz : Whz; cc = nout; }
        else           { W = (kb < 2) ? Wxr : Whr; cc = nout - 64; }
        float v = W[(kb & 1) * 4096 + kr * 64 + cc];
        __nv_bfloat16 hb = __float2bfloat16(v);
        __nv_bfloat16 lb = __float2bfloat16(v - __bfloat162float(hb));
        int base = kb * 16384 + kr * 128 + nout;
        g_Bzr[base]        = hb;
        g_Bzr[base + 8192] = lb;
    }
    for (size_t i = gid; i < 256 * 64; i += stride) {
        int k = (int)(i >> 6), nout = (int)(i & 63);
        int kb = k >> 6, kr = k & 63;
        const float* W = (kb < 2) ? Wxh : Whh;
        float v = W[(kb & 1) * 4096 + kr * 64 + nout];
        __nv_bfloat16 hb = __float2bfloat16(v);
        __nv_bfloat16 lb = __float2bfloat16(v - __bfloat162float(hb));
        int base = kb * 8192 + kr * 64 + nout;
        g_Bh[base]        = hb;
        g_Bh[base + 4096] = lb;
    }
    for (size_t i = gid; i < 64; i += stride) {
        g_bz[i] = bxz[i] + bhz[i];
        g_br[i] = bxr[i] + bhr[i];
        g_bh[i] = bxh[i] + bhh[i];
    }
}

// ---------------- setup kernels ----------------
__global__ void k_hist(const void* __restrict__ ei, int E) {
    int e = blockIdx.x * blockDim.x + threadIdx.x;
    if (e < E) {
        int s = load_idx(ei, e);
        int d = load_idx(ei, (size_t)E + e);
        if (s >= 0 && s < NN) atomicAdd(&g_deg[s], 1);
        if (d >= 0 && d < NN) atomicAdd(&g_cnt[d], 1);
    }
}
__global__ void k_dinv(int n) {
    int i = blockIdx.x * blockDim.x + threadIdx.x;
    if (i < n) {
        int d = g_deg[i];
        g_dinv[i] = (d > 0) ? rsqrtf((float)d) : 0.0f;
    }
}
__global__ void k_scan1(int n) {
    __shared__ int s[1024];
    int tid = threadIdx.x;
    int gid = blockIdx.x * 1024 + tid;
    int v = (gid < n) ? g_cnt[gid] : 0;
    s[tid] = v;
    __syncthreads();
    #pragma unroll
    for (int off = 1; off < 1024; off <<= 1) {
        int t = (tid >= off) ? s[tid - off] : 0;
        __syncthreads();
        s[tid] += t;
        __syncthreads();
    }
    if (gid < n) g_rowptr[gid] = s[tid] - v;
    if (tid == 1023) g_bsum[blockIdx.x] = s[1023];
}
__global__ void k_scan2(int nb) {
    if (threadIdx.x == 0) {
        int acc = 0;
        for (int i = 0; i < nb; i++) { int t = g_bsum[i]; g_boff[i] = acc; acc += t; }
    }
}
__global__ void k_scan3(int n, int E) {
    int gid = blockIdx.x * blockDim.x + threadIdx.x;
    if (gid < n) g_rowptr[gid] += g_boff[gid >> 10];
    if (gid == 0) g_rowptr[n] = E;
}
__global__ void k_fill(const void* __restrict__ ei, int E) {
    int e = blockIdx.x * blockDim.x + threadIdx.x;
    if (e >= E) return;
    int s = load_idx(ei, e);
    int d = load_idx(ei, (size_t)E + e);
    if (s < 0 || s >= NN || d < 0 || d >= NN) return;
    int pos = g_rowptr[d] + atomicAdd(&g_cursor[d], 1);
    float w = -g_dinv[s] * g_dinv[d];
    g_cw[pos] = make_int2(s, __float_as_int(w));
}

// ---------------- spmv: warp per row, uint2 lanes, 4-edge unroll -----------
__device__ __forceinline__ void spmv_warp(const uint32_t* __restrict__ x,
                                          uint32_t* __restrict__ y,
                                          int row, int lane) {
    const uint2* x2 = reinterpret_cast<const uint2*>(x);
    int s = g_rowptr[row], e = g_rowptr[row + 1];
    float a0 = 0.0f, a1 = 0.0f;
    int p = s;
    for (; p + 4 <= e; p += 4) {
        int2 c0 = g_cw[p], c1 = g_cw[p + 1], c2 = g_cw[p + 2], c3 = g_cw[p + 3];
        uint2 v0 = __ldg(&x2[(size_t)c0.x * 32 + lane]);
        uint2 v1 = __ldg(&x2[(size_t)c1.x * 32 + lane]);
        uint2 v2 = __ldg(&x2[(size_t)c2.x * 32 + lane]);
        uint2 v3 = __ldg(&x2[(size_t)c3.x * 32 + lane]);
        float w0 = __int_as_float(c0.y), w1 = __int_as_float(c1.y);
        float w2 = __int_as_float(c2.y), w3 = __int_as_float(c3.y);
        a0 = fmaf(w0, unpack_bf2(v0.x), a0); a1 = fmaf(w0, unpack_bf2(v0.y), a1);
        a0 = fmaf(w1, unpack_bf2(v1.x), a0); a1 = fmaf(w1, unpack_bf2(v1.y), a1);
        a0 = fmaf(w2, unpack_bf2(v2.x), a0); a1 = fmaf(w2, unpack_bf2(v2.y), a1);
        a0 = fmaf(w3, unpack_bf2(v3.x), a0); a1 = fmaf(w3, unpack_bf2(v3.y), a1);
    }
    for (; p < e; p++) {
        int2 c = g_cw[p];
        uint2 v = __ldg(&x2[(size_t)c.x * 32 + lane]);
        float w = __int_as_float(c.y);
        a0 = fmaf(w, unpack_bf2(v.x), a0);
        a1 = fmaf(w, unpack_bf2(v.y), a1);
    }
    uint2 o = make_uint2(pack_bf2(a0), pack_bf2(a1));
    reinterpret_cast<uint2*>(y)[(size_t)row * 32 + lane] = o;
}

__global__ void k_spmv2(const uint32_t* __restrict__ x, uint32_t* __restrict__ y, int n) {
    int row = blockIdx.x * 8 + (threadIdx.x >> 5);
    if (row >= n) return;
    spmv_warp(x, y, row, threadIdx.x & 31);
}

__global__ void k_spmv2_all(int n) {
    int row = blockIdx.x * 8 + (threadIdx.x >> 5);
    if (row >= n) return;
    int t = blockIdx.y;
    spmv_warp(g_X2 + (size_t)t * n * 64, g_mvxA + (size_t)t * n * 64, row, threadIdx.x & 31);
}

// ---------------- mma.sync GEMM core (bf2 inputs), smem W ----------------
// C(BM x BN) = [A0|A1|A2|A3](BM x 256) @ W(256 x BN), bf16 3-split.
// Each warp: 16 rows x 64 cols -> acc[8][4] (32 regs).
template <int BM, int BN, int THREADS>
__device__ __forceinline__ void mma_core(
    const uint32_t* __restrict__ A0, const uint32_t* __restrict__ A1,
    const uint32_t* __restrict__ A2, const uint32_t* __restrict__ A3,
    const __nv_bfloat16* __restrict__ Bpk, int n,
    int warpRow, int warpCol, float (&acc)[8][4], char* sm)
{
    constexpr int ASTR = 72;
    constexpr int A_BYTES = BM * ASTR * 2;
    constexpr int WSTR = BN + 8;
    constexpr int W_BYTES = 64 * WSTR * 2;
    constexpr int W_OFF = 2 * A_BYTES;

    const int tid = threadIdx.x;
    const int lane = tid & 31;
    uint32_t s_a = smem_u32(sm);
    uint32_t s_w = s_a + W_OFF;

    const uint32_t* srcs[4] = {A0, A1, A2, A3};

    #pragma unroll 1
    for (int c = 0; c < 4; c++) {
        if (c) __syncthreads();

        // ---- A chunk: BM x 64 bf2 -> hi/lo bf16 tiles (prmt only) ----
        const uint32_t* src = srcs[c];
        constexpr int GROUPS = BM * 64 / (THREADS * 8);
        #pragma unroll
        for (int g = 0; g < GROUPS; g++) {
            int gi = g * THREADS + tid;
            int r  = gi >> 3;
            int kc = (gi & 7) * 8;
            int gr = blockIdx.x * BM + r;
            uint4 p0 = make_uint4(0, 0, 0, 0), p1 = make_uint4(0, 0, 0, 0);
            if (gr < n) {
                p0 = *reinterpret_cast<const uint4*>(src + (size_t)gr * 64 + kc);
                p1 = *reinterpret_cast<const uint4*>(src + (size_t)gr * 64 + kc + 4);
            }
            uint4 hv, lv;
            hv.x = __byte_perm(p0.x, p0.y, 0x5410);
            hv.y = __byte_perm(p0.z, p0.w, 0x5410);
            hv.z = __byte_perm(p1.x, p1.y, 0x5410);
            hv.w = __byte_perm(p1.z, p1.w, 0x5410);
            lv.x = __byte_perm(p0.x, p0.y, 0x7632);
            lv.y = __byte_perm(p0.z, p0.w, 0x7632);
            lv.z = __byte_perm(p1.x, p1.y, 0x7632);
            lv.w = __byte_perm(p1.z, p1.w, 0x7632);
            uint32_t off = (uint32_t)(r * ASTR + kc) * 2;
            *reinterpret_cast<uint4*>(sm + off)           = hv;
            *reinterpret_cast<uint4*>(sm + A_BYTES + off) = lv;
        }

        // ---- W chunk: linear global -> padded smem ----
        {
            const uint4* bs = reinterpret_cast<const uint4*>(Bpk + (size_t)c * 2 * 64 * BN);
            constexpr int ROWU4 = BN / 8;
            constexpr int TOT = 64 * ROWU4;
            #pragma unroll
            for (int sel = 0; sel < 2; sel++) {
                char* wd = sm + W_OFF + sel * W_BYTES;
                #pragma unroll
                for (int it = 0; it < TOT / THREADS; it++) {
                    int u = tid + it * THREADS;
                    int k = u / ROWU4, q = u % ROWU4;
                    *reinterpret_cast<uint4*>(wd + k * WSTR * 2 + q * 16) = bs[sel * TOT + u];
                }
            }
        }
        __syncthreads();

        // ---- compute: 4 ksteps of 16 ----
        #pragma unroll
        for (int ks = 0; ks < 4; ks++) {
            const int k0 = ks * 16;
            uint32_t ah[4], al[4];
            {
                int rowoff = warpRow + ((lane >> 3) & 1) * 8 + (lane & 7);
                int coloff = k0 + (lane >> 4) * 8;
                uint32_t ad = s_a + (uint32_t)(rowoff * ASTR + coloff) * 2;
                ldm_x4(ah, ad);
                ldm_x4(al, ad + A_BYTES);
            }
            #pragma unroll
            for (int nb2 = 0; nb2 < 4; nb2++) {
                int n0 = warpCol + nb2 * 16;
                uint32_t bd = s_w + (uint32_t)((k0 + (lane & 15)) * WSTR + n0 + (lane >> 4) * 8) * 2;
                uint32_t bh[4], bl[4];
                ldm_x4t(bh, bd);
                ldm_x4t(bl, bd + W_BYTES);
                mma16816(acc[2 * nb2 + 0], ah, bh[0], bh[1]);
                mma16816(acc[2 * nb2 + 0], al, bh[0], bh[1]);
                mma16816(acc[2 * nb2 + 0], ah, bl[0], bl[1]);
                mma16816(acc[2 * nb2 + 1], ah, bh[2], bh[3]);
                mma16816(acc[2 * nb2 + 1], al, bh[2], bh[3]);
                mma16816(acc[2 * nb2 + 1], ah, bl[2], bl[3]);
            }
        }
    }
}

__device__ __forceinline__ float sigmoidf_(float x) { return 1.0f / (1.0f + expf(-x)); }

// z/r GEMM: A = [x_t | mvx | h | mvh], W = g_Bzr (256x128); BM=64, 8 warps.
__global__ __launch_bounds__(256)
void k_gemm_zr_mma(const uint32_t* __restrict__ xt, const uint32_t* __restrict__ mvx, int n) {
    extern __shared__ char sm[];
    const int w = threadIdx.x >> 5, lane = threadIdx.x & 31;
    const int warpRow = (w & 3) * 16;
    const int warpCol = (w >> 2) * 64;
    float acc[8][4] = {};
    mma_core<64, 128, 256>(xt, mvx, g_h2, g_mvh2, g_Bzr, n, warpRow, warpCol, acc, sm);

    const bool isZ = (warpCol == 0);
    const int rbase = blockIdx.x * 64 + warpRow;
    #pragma unroll
    for (int h2 = 0; h2 < 2; h2++) {
        int row = rbase + (lane >> 2) + h2 * 8;
        if (row >= n) continue;
        #pragma unroll
        for (int nb = 0; nb < 8; nb++) {
            int cc = nb * 8 + (lane & 3) * 2;
            float v0 = acc[nb][h2 * 2 + 0];
            float v1 = acc[nb][h2 * 2 + 1];
            if (isZ) {
                float2 o;
                o.x = sigmoidf_(v0 + g_bz[cc]);
                o.y = sigmoidf_(v1 + g_bz[cc + 1]);
                *reinterpret_cast<float2*>(&g_z[(size_t)row * 64 + cc]) = o;
            } else {
                float2 hv = *reinterpret_cast<const float2*>(&g_h[(size_t)row * 64 + cc]);
                float r0 = sigmoidf_(v0 + g_br[cc])     * hv.x;
                float r1 = sigmoidf_(v1 + g_br[cc + 1]) * hv.y;
                uint2 o = make_uint2(pack_bf2(r0), pack_bf2(r1));
                *reinterpret_cast<uint2*>(&g_hr2[(size_t)row * 64 + cc]) = o;
            }
        }
    }
}

// h GEMM: A = [x_t | mvx | hr | mvhr], W = g_Bh (256x64); BM=128, 8 warps.
// Each warp: rows w*16..w*16+15, all 64 cols. Halves grid + W-fill traffic.
__global__ __launch_bounds__(256)
void k_gemm_h_mma(const uint32_t* __restrict__ xt, const uint32_t* __restrict__ mvx, int n) {
    extern __shared__ char sm[];
    const int w = threadIdx.x >> 5, lane = threadIdx.x & 31;
    float acc[8][4] = {};
    mma_core<128, 64, 256>(xt, mvx, g_hr2, g_mvhr2, g_Bh, n, w * 16, 0, acc, sm);

    const int rbase = blockIdx.x * 128 + w * 16;
    #pragma unroll
    for (int h2 = 0; h2 < 2; h2++) {
        int row = rbase + (lane >> 2) + h2 * 8;
        if (row >= n) continue;
        #pragma unroll
        for (int nb = 0; nb < 8; nb++) {
            int cc = nb * 8 + (lane & 3) * 2;
            float t0 = tanhf(acc[nb][h2 * 2 + 0] + g_bh[cc]);
            float t1 = tanhf(acc[nb][h2 * 2 + 1] + g_bh[cc + 1]);
            float2 zv = *reinterpret_cast<const float2*>(&g_z[(size_t)row * 64 + cc]);
            float2 hv = *reinterpret_cast<const float2*>(&g_h[(size_t)row * 64 + cc]);
            float2 o;
            o.x = zv.x * hv.x + (1.0f - zv.x) * t0;
            o.y = zv.y * hv.y + (1.0f - zv.y) * t1;
            *reinterpret_cast<float2*>(&g_h[(size_t)row * 64 + cc]) = o;
            uint2 o2 = make_uint2(pack_bf2(o.x), pack_bf2(o.y));
            *reinterpret_cast<uint2*>(&g_h2[(size_t)row * 64 + cc]) = o2;
        }
    }
}

// ---------------- final linear: out = h @ Wlin + blin (Nx64 @ 64x16) --------
__global__ __launch_bounds__(256)
void k_out(const float* __restrict__ Wlin, const float* __restrict__ blin,
           float* __restrict__ out, int n) {
    __shared__ float Ws[64][16];
    __shared__ float Hs[16][64];
    int tid = threadIdx.x;
    int rowBase = blockIdx.x * 16;
    #pragma unroll
    for (int i = 0; i < 4; i++) {
        int idx = tid + i * 256;
        reinterpret_cast<float*>(Ws)[idx] = Wlin[idx];
    }
    {
        int r = tid >> 4, c4 = tid & 15;
        int gr = rowBase + r;
        float4 v = make_float4(0.f, 0.f, 0.f, 0.f);
        if (gr < n) v = *reinterpret_cast<const float4*>(g_h + (size_t)gr * 64 + c4 * 4);
        *reinterpret_cast<float4*>(&Hs[r][c4 * 4]) = v;
    }
    __syncthreads();
    int r = tid >> 4, c = tid & 15;
    float s = blin[c];
    #pragma unroll
    for (int k = 0; k < 64; k++) s += Hs[r][k] * Ws[k][c];
    int gr = rowBase + r;
    if (gr < n) out[(size_t)gr * 16 + c] = s;
}

// ---------------- host orchestration (graph-capturable) ----------------
extern "C" void kernel_launch(void* const* d_in, const int* in_sizes, int n_in,
                              void* d_out, int out_size) {
    const float* X  = (const float*)d_in[0];
    const void*  EI = d_in[1];
    const float* Wxz = (const float*)d_in[2];
    const float* bxz = (const float*)d_in[3];
    const float* Whz = (const float*)d_in[4];
    const float* bhz = (const float*)d_in[5];
    const float* Wxr = (const float*)d_in[6];
    const float* bxr = (const float*)d_in[7];
    const float* Whr = (const float*)d_in[8];
    const float* bhr = (const float*)d_in[9];
    const float* Wxh = (const float*)d_in[10];
    const float* bxh = (const float*)d_in[11];
    const float* Whh = (const float*)d_in[12];
    const float* bhh = (const float*)d_in[13];
    const float* Wlin = (const float*)d_in[14];
    const float* blin = (const float*)d_in[15];
    float* out = (float*)d_out;

    const int n = NN;
    const int E = in_sizes[1] / 2;

    uint32_t *p_X2, *p_mvxA, *p_h2, *p_mvh2, *p_hr2, *p_mvhr2;
    cudaGetSymbolAddress((void**)&p_X2,    g_X2);
    cudaGetSymbolAddress((void**)&p_mvxA,  g_mvxA);
    cudaGetSymbolAddress((void**)&p_h2,    g_h2);
    cudaGetSymbolAddress((void**)&p_mvh2,  g_mvh2);
    cudaGetSymbolAddress((void**)&p_hr2,   g_hr2);
    cudaGetSymbolAddress((void**)&p_mvhr2, g_mvhr2);

    // zr: BM=64 (A 2*9216, W 2*64*136*2); h: BM=128 (A 2*18432, W 2*64*72*2)
    const int SMEM_ZR = 2 * 9216 + 2 * 64 * (128 + 8) * 2;    // 53248
    const int SMEM_H  = 2 * 18432 + 2 * 64 * (64 + 8) * 2;    // 55296
    cudaFuncSetAttribute(k_gemm_zr_mma, cudaFuncAttributeMaxDynamicSharedMemorySize, SMEM_ZR);
    cudaFuncSetAttribute(k_gemm_h_mma,  cudaFuncAttributeMaxDynamicSharedMemorySize, SMEM_H);

    int ggrid  = (n + 63) / 64;     // zr grid
    int hgrid  = (n + 127) / 128;   // h grid
    int nb = (n + 1023) / 1024;

    // setup
    k_init<<<2048, 256>>>(X, (const int*)EI, Wxz, Whz, Wxr, Whr, Wxh, Whh,
                          bxz, bhz, bxr, bhr, bxh, bhh);
    k_hist<<<(E + 255) / 256, 256>>>(EI, E);
    k_dinv<<<(n + 255) / 256, 256>>>(n);
    k_scan1<<<nb, 1024>>>(n);
    k_scan2<<<1, 32>>>(nb);
    k_scan3<<<(n + 255) / 256, 256>>>(n, E);
    k_fill<<<(E + 255) / 256, 256>>>(EI, E);

    int sgrid = (n + 7) / 8;
    k_spmv2_all<<<dim3(sgrid, TT), 256>>>(n);

    for (int t = 0; t < TT; t++) {
        const uint32_t* xt  = p_X2   + (size_t)t * n * 64;
        const uint32_t* mvx = p_mvxA + (size_t)t * n * 64;
        k_spmv2<<<sgrid, 256>>>(p_h2, p_mvh2, n);
        k_gemm_zr_mma<<<ggrid, 256, SMEM_ZR>>>(xt, mvx, n);
        k_spmv2<<<sgrid, 256>>>(p_hr2, p_mvhr2, n);
        k_gemm_h_mma<<<hgrid, 256, SMEM_H>>>(xt, mvx, n);
    }

    k_out<<<(n + 15) / 16, 256>>>(Wlin, blin, out, n);
}